// round 1
// baseline (speedup 1.0000x reference)
#include <cuda_runtime.h>
#include <cuda_bf16.h>
#include <cstddef>

#define B_ 4
#define T_ 2048
#define D_ 1024

// Scratch (allocation-free rule: __device__ globals)
__device__ float g_q[(size_t)B_ * T_ * D_];
__device__ float g_k[(size_t)B_ * T_ * D_];
__device__ float g_v[(size_t)B_ * T_ * D_];
__device__ float g_s[(size_t)B_ * T_ * T_];

constexpr int BM = 128, BN = 128, BK = 8;

// ---------------------------------------------------------------------------
// NN GEMM: C[M,N] = A[M,K] @ B[K,N] (+bias). CAUSAL limits K-loop to the tile's
// row range (valid because P rows are zero-padded past the diagonal).
// blockIdx.z selects batch via strides sA/sB/sC.
// ---------------------------------------------------------------------------
template <bool BIAS, bool CAUSAL>
__global__ __launch_bounds__(256) void gemm_nn(
    const float* __restrict__ A, const float* __restrict__ Bm,
    const float* __restrict__ bias, float* __restrict__ C,
    int M, int N, int K, size_t sA, size_t sB, size_t sC)
{
    A  += (size_t)blockIdx.z * sA;
    Bm += (size_t)blockIdx.z * sB;
    C  += (size_t)blockIdx.z * sC;

    const int m0 = blockIdx.y * BM;
    const int n0 = blockIdx.x * BN;

    int Keff = K;
    if (CAUSAL) { int lim = m0 + BM; Keff = lim < K ? lim : K; }
    const int ktiles = Keff / BK;

    __shared__ float As[2][BK][BM];
    __shared__ float Bs[2][BK][BN];

    const int tid = threadIdx.x;
    const int tx = tid & 15;        // 0..15  -> 8 cols each
    const int ty = tid >> 4;        // 0..15  -> 8 rows each

    // A loader: 128 rows x 8 k -> 2 float4 per row, 256 float4 total
    const int aRow = tid >> 1;
    const int aCol = (tid & 1) * 4;
    // B loader: 8 rows x 128 cols -> 256 float4
    const int bRow = tid >> 5;
    const int bCol = (tid & 31) * 4;

    const float* Aptr = A + (size_t)(m0 + aRow) * K + aCol;
    const float* Bptr = Bm + (size_t)bRow * N + n0 + bCol;

    float4 av = *(const float4*)Aptr;
    float4 bv = *(const float4*)Bptr;
    As[0][aCol + 0][aRow] = av.x;
    As[0][aCol + 1][aRow] = av.y;
    As[0][aCol + 2][aRow] = av.z;
    As[0][aCol + 3][aRow] = av.w;
    *(float4*)&Bs[0][bRow][bCol] = bv;
    __syncthreads();

    float acc[8][8] = {};
    int buf = 0;

    for (int kt = 0; kt < ktiles; kt++) {
        const bool more = (kt + 1 < ktiles);
        if (more) {
            av = *(const float4*)(Aptr + (size_t)(kt + 1) * BK);
            bv = *(const float4*)(Bptr + (size_t)(kt + 1) * BK * N);
        }
#pragma unroll
        for (int kk = 0; kk < BK; kk++) {
            float a[8], b[8];
#pragma unroll
            for (int i = 0; i < 8; i++) a[i] = As[buf][kk][ty * 8 + i];
#pragma unroll
            for (int j = 0; j < 8; j++) b[j] = Bs[buf][kk][tx * 8 + j];
#pragma unroll
            for (int i = 0; i < 8; i++)
#pragma unroll
                for (int j = 0; j < 8; j++)
                    acc[i][j] += a[i] * b[j];
        }
        if (more) {
            const int nb = buf ^ 1;
            As[nb][aCol + 0][aRow] = av.x;
            As[nb][aCol + 1][aRow] = av.y;
            As[nb][aCol + 2][aRow] = av.z;
            As[nb][aCol + 3][aRow] = av.w;
            *(float4*)&Bs[nb][bRow][bCol] = bv;
            __syncthreads();
            buf = nb;
        }
    }

#pragma unroll
    for (int i = 0; i < 8; i++) {
        const int m = m0 + ty * 8 + i;
        float* crow = C + (size_t)m * N + n0 + tx * 8;
        float4 v0, v1;
        float out[8];
#pragma unroll
        for (int j = 0; j < 8; j++) {
            float v = acc[i][j];
            if (BIAS) v += bias[n0 + tx * 8 + j];
            out[j] = v;
        }
        v0.x = out[0]; v0.y = out[1]; v0.z = out[2]; v0.w = out[3];
        v1.x = out[4]; v1.y = out[5]; v1.z = out[6]; v1.w = out[7];
        *(float4*)(crow)     = v0;
        *(float4*)(crow + 4) = v1;
    }
}

// ---------------------------------------------------------------------------
// NT GEMM: C[M,N] = scale * (A[M,K] @ B[N,K]^T). Used for S = Q K^T / sqrt(d).
// Upper-triangle tiles (n0 > m0+BM-1) skipped entirely — softmax never reads
// s > t, so those entries can stay garbage.
// ---------------------------------------------------------------------------
__global__ __launch_bounds__(256) void gemm_nt_scaled(
    const float* __restrict__ A, const float* __restrict__ Bm,
    float* __restrict__ C, int M, int N, int K, float scale,
    size_t sA, size_t sB, size_t sC)
{
    const int m0 = blockIdx.y * BM;
    const int n0 = blockIdx.x * BN;
    if (n0 > m0 + BM - 1) return;   // fully above the causal diagonal

    A  += (size_t)blockIdx.z * sA;
    Bm += (size_t)blockIdx.z * sB;
    C  += (size_t)blockIdx.z * sC;

    const int ktiles = K / BK;

    __shared__ float As[2][BK][BM];
    __shared__ float Bs[2][BK][BN];

    const int tid = threadIdx.x;
    const int tx = tid & 15;
    const int ty = tid >> 4;

    const int aRow = tid >> 1;
    const int aCol = (tid & 1) * 4;

    const float* Aptr = A + (size_t)(m0 + aRow) * K + aCol;
    const float* Bptr = Bm + (size_t)(n0 + aRow) * K + aCol;  // same pattern: row=n, col=k

    float4 av = *(const float4*)Aptr;
    float4 bv = *(const float4*)Bptr;
    As[0][aCol + 0][aRow] = av.x;
    As[0][aCol + 1][aRow] = av.y;
    As[0][aCol + 2][aRow] = av.z;
    As[0][aCol + 3][aRow] = av.w;
    Bs[0][aCol + 0][aRow] = bv.x;
    Bs[0][aCol + 1][aRow] = bv.y;
    Bs[0][aCol + 2][aRow] = bv.z;
    Bs[0][aCol + 3][aRow] = bv.w;
    __syncthreads();

    float acc[8][8] = {};
    int buf = 0;

    for (int kt = 0; kt < ktiles; kt++) {
        const bool more = (kt + 1 < ktiles);
        if (more) {
            av = *(const float4*)(Aptr + (size_t)(kt + 1) * BK);
            bv = *(const float4*)(Bptr + (size_t)(kt + 1) * BK);
        }
#pragma unroll
        for (int kk = 0; kk < BK; kk++) {
            float a[8], b[8];
#pragma unroll
            for (int i = 0; i < 8; i++) a[i] = As[buf][kk][ty * 8 + i];
#pragma unroll
            for (int j = 0; j < 8; j++) b[j] = Bs[buf][kk][tx * 8 + j];
#pragma unroll
            for (int i = 0; i < 8; i++)
#pragma unroll
                for (int j = 0; j < 8; j++)
                    acc[i][j] += a[i] * b[j];
        }
        if (more) {
            const int nb = buf ^ 1;
            As[nb][aCol + 0][aRow] = av.x;
            As[nb][aCol + 1][aRow] = av.y;
            As[nb][aCol + 2][aRow] = av.z;
            As[nb][aCol + 3][aRow] = av.w;
            Bs[nb][aCol + 0][aRow] = bv.x;
            Bs[nb][aCol + 1][aRow] = bv.y;
            Bs[nb][aCol + 2][aRow] = bv.z;
            Bs[nb][aCol + 3][aRow] = bv.w;
            __syncthreads();
            buf = nb;
        }
    }

#pragma unroll
    for (int i = 0; i < 8; i++) {
        const int m = m0 + ty * 8 + i;
        float* crow = C + (size_t)m * N + n0 + tx * 8;
        float4 v0, v1;
        v0.x = acc[i][0] * scale; v0.y = acc[i][1] * scale;
        v0.z = acc[i][2] * scale; v0.w = acc[i][3] * scale;
        v1.x = acc[i][4] * scale; v1.y = acc[i][5] * scale;
        v1.z = acc[i][6] * scale; v1.w = acc[i][7] * scale;
        *(float4*)(crow)     = v0;
        *(float4*)(crow + 4) = v1;
    }
}

// ---------------------------------------------------------------------------
// Causal row softmax, in place. One block per (t, b) row; row staged in smem.
// Writes zeros for s > t so the PV GEMM can run a full (K-limited) loop.
// ---------------------------------------------------------------------------
__global__ __launch_bounds__(256) void softmax_causal(float* __restrict__ S)
{
    const int t = blockIdx.x;
    const int b = blockIdx.y;
    float* row = S + ((size_t)b * T_ + t) * T_;
    const int L = t + 1;
    const int tid = threadIdx.x;

    __shared__ float buf[T_];
    __shared__ float red[256];

    float mx = -1e30f;
    for (int s = tid; s < L; s += 256) {
        float v = row[s];
        buf[s] = v;
        mx = fmaxf(mx, v);
    }
    red[tid] = mx;
    __syncthreads();
    for (int off = 128; off > 0; off >>= 1) {
        if (tid < off) red[tid] = fmaxf(red[tid], red[tid + off]);
        __syncthreads();
    }
    const float m = red[0];
    __syncthreads();

    float sum = 0.f;
    for (int s = tid; s < L; s += 256) {
        float e = __expf(buf[s] - m);
        buf[s] = e;
        sum += e;
    }
    red[tid] = sum;
    __syncthreads();
    for (int off = 128; off > 0; off >>= 1) {
        if (tid < off) red[tid] += red[tid + off];
        __syncthreads();
    }
    const float inv = 1.0f / red[0];
    __syncthreads();

    for (int s = tid; s < L; s += 256) row[s] = buf[s] * inv;
    for (int s = L + tid; s < T_; s += 256) row[s] = 0.f;
}

// ---------------------------------------------------------------------------
extern "C" void kernel_launch(void* const* d_in, const int* in_sizes, int n_in,
                              void* d_out, int out_size)
{
    const float* x  = (const float*)d_in[0];
    const float* Wq = (const float*)d_in[1];
    const float* bq = (const float*)d_in[2];
    const float* Wk = (const float*)d_in[3];
    const float* bk = (const float*)d_in[4];
    const float* Wv = (const float*)d_in[5];
    const float* bv = (const float*)d_in[6];
    float* out = (float*)d_out;

    float *q, *k, *v, *s;
    cudaGetSymbolAddress((void**)&q, g_q);
    cudaGetSymbolAddress((void**)&k, g_k);
    cudaGetSymbolAddress((void**)&v, g_v);
    cudaGetSymbolAddress((void**)&s, g_s);

    const int M = B_ * T_;  // 8192

    // 1) QKV projections
    dim3 gProj(D_ / BN, M / BM, 1);
    gemm_nn<true, false><<<gProj, 256>>>(x, Wq, bq, q, M, D_, D_, 0, 0, 0);
    gemm_nn<true, false><<<gProj, 256>>>(x, Wk, bk, k, M, D_, D_, 0, 0, 0);
    gemm_nn<true, false><<<gProj, 256>>>(x, Wv, bv, v, M, D_, D_, 0, 0, 0);

    // 2) S = Q K^T / sqrt(D)  (lower-triangle tiles only)
    dim3 gS(T_ / BN, T_ / BM, B_);
    gemm_nt_scaled<<<gS, 256>>>(q, k, s, T_, T_, D_, 1.0f / 32.0f,
                                (size_t)T_ * D_, (size_t)T_ * D_, (size_t)T_ * T_);

    // 3) causal softmax in place (zero-fills masked tail)
    softmax_causal<<<dim3(T_, B_), 256>>>(s);

    // 4) out = P V (K-loop limited by causality)
    dim3 gPV(D_ / BN, T_ / BM, B_);
    gemm_nn<false, true><<<gPV, 256>>>(s, v, nullptr, out, T_, D_, T_,
                                       (size_t)T_ * T_, (size_t)T_ * D_, (size_t)T_ * D_);
}

// round 3
// speedup vs baseline: 5.3632x; 5.3632x over previous
#include <cuda_runtime.h>
#include <cuda_bf16.h>
#include <cstdint>
#include <cstddef>

#define B_ 4
#define T_ 2048
#define D_ 1024

// ---------------------------------------------------------------------------
// Scratch (__device__ globals: allocation-free rule)
// ---------------------------------------------------------------------------
__device__ float g_xr[(size_t)B_ * T_ * D_];          // x rounded to tf32
__device__ float g_wt[3][(size_t)D_ * D_];            // W^T rounded (q,k,v)
__device__ float g_q [(size_t)B_ * T_ * D_];          // q (tf32-rounded)
__device__ float g_k [(size_t)B_ * T_ * D_];          // k (tf32-rounded)
__device__ float g_v [(size_t)B_ * T_ * D_];          // v (fp32)
__device__ float g_vt[(size_t)B_ * D_ * T_];          // v^T (tf32-rounded)
__device__ float g_s [(size_t)B_ * T_ * T_];          // scores / probs

__device__ __forceinline__ float rna_tf32(float x) {
    uint32_t u;
    asm("cvt.rna.tf32.f32 %0, %1;" : "=r"(u) : "f"(x));
    return __uint_as_float(u);
}

#define CP_ASYNC16(dst, src) \
    asm volatile("cp.async.cg.shared.global [%0], [%1], 16;" :: "r"(dst), "l"(src) : "memory")
#define CP_COMMIT()  asm volatile("cp.async.commit_group;" ::: "memory")
#define CP_WAIT1()   asm volatile("cp.async.wait_group 1;" ::: "memory")
#define CP_WAIT0()   asm volatile("cp.async.wait_group 0;" ::: "memory")

__device__ __forceinline__ uint32_t smem_u32(const void* p) {
    uint32_t a;
    asm("{ .reg .u64 t; cvta.to.shared.u64 t, %1; cvt.u32.u64 %0, t; }" : "=r"(a) : "l"(p));
    return a;
}

// m16n8k8 tf32 mma: D = A@B + D (fp32 accum). a: 4 regs, b: 2 regs, c: 4 regs.
__device__ __forceinline__ void mma_tf32(
    float& c0, float& c1, float& c2, float& c3,
    uint32_t a0, uint32_t a1, uint32_t a2, uint32_t a3,
    uint32_t b0, uint32_t b1)
{
    asm volatile(
        "mma.sync.aligned.m16n8k8.row.col.f32.tf32.tf32.f32 "
        "{%0,%1,%2,%3}, {%4,%5,%6,%7}, {%8,%9}, {%0,%1,%2,%3};"
        : "+f"(c0), "+f"(c1), "+f"(c2), "+f"(c3)
        : "r"(a0), "r"(a1), "r"(a2), "r"(a3), "r"(b0), "r"(b1));
}

// ---------------------------------------------------------------------------
// tf32 tensor GEMM: C[M,N] = A[M,K] @ Bm[N,K]^T (both row-major, K-major tiles)
// 128x128x32 block tile, 8 warps in 2(m) x 4(n) grid -> 64x32 warp tile.
// Double-buffered cp.async, smem rows padded to 36 floats (conflict-free frags)
// ---------------------------------------------------------------------------
constexpr int BM = 128, BN = 128, BK = 32;
constexpr int LDR = 36;                       // floats per smem row (pad 32->36)
constexpr int TILE_FLOATS = BM * LDR;         // 4608 per operand
constexpr int STAGE_FLOATS = 2 * TILE_FLOATS; // A + B
constexpr int SMEM_BYTES = 2 * STAGE_FLOATS * 4;  // 73728

template <bool BIAS, bool SCALE, bool CSKIP, bool KLIM, bool ROUND>
__global__ __launch_bounds__(256, 2) void gemm_tc(
    const float* __restrict__ A, const float* __restrict__ Bm,
    const float* __restrict__ bias, float* __restrict__ C,
    int M, int N, int K, float scale, size_t sA, size_t sB, size_t sC)
{
    const int m0 = blockIdx.y * BM;
    const int n0 = blockIdx.x * BN;
    if (CSKIP && n0 >= m0 + BM) return;       // fully above causal diagonal

    A  += (size_t)blockIdx.z * sA;
    Bm += (size_t)blockIdx.z * sB;
    C  += (size_t)blockIdx.z * sC;

    int Keff = K;
    if (KLIM) { int lim = m0 + BM; Keff = lim < K ? lim : K; }
    const int KT = Keff / BK;

    extern __shared__ float sm[];
    const uint32_t sm_b = smem_u32(sm);

    const int tid = threadIdx.x;
    const int wid = tid >> 5;
    const int lid = tid & 31;
    const int wm = wid >> 2;                  // 0..1
    const int wn = wid & 3;                   // 0..3
    const int g  = lid >> 2;                  // 0..7
    const int t4 = lid & 3;                   // 0..3

    // Stage loader: A tile 128x32 + B tile 128x32, 16B chunks, 8 per thread.
    auto load_stage = [&](int stage, int kt) {
        const uint32_t ab = sm_b + stage * STAGE_FLOATS * 4;
        const uint32_t bb = ab + TILE_FLOATS * 4;
        const float* Ag = A + (size_t)m0 * K + kt * BK;
        const float* Bg = Bm + (size_t)n0 * K + kt * BK;
#pragma unroll
        for (int i = 0; i < 4; i++) {
            int idx = i * 256 + tid;          // 0..1023
            int row = idx >> 3, c = idx & 7;
            uint32_t off = (uint32_t)(row * LDR + c * 4) * 4;
            CP_ASYNC16(ab + off, Ag + (size_t)row * K + c * 4);
            CP_ASYNC16(bb + off, Bg + (size_t)row * K + c * 4);
        }
    };

    load_stage(0, 0);
    CP_COMMIT();
    if (KT > 1) { load_stage(1, 1); CP_COMMIT(); }

    float acc[4][4][4];
#pragma unroll
    for (int i = 0; i < 4; i++)
#pragma unroll
        for (int j = 0; j < 4; j++)
#pragma unroll
            for (int r = 0; r < 4; r++) acc[i][j][r] = 0.f;

    for (int kt = 0; kt < KT; kt++) {
        if (kt + 1 < KT) CP_WAIT1(); else CP_WAIT0();
        __syncthreads();

        const uint32_t* As = (const uint32_t*)(sm + (kt & 1) * STAGE_FLOATS);
        const uint32_t* Bs = As + TILE_FLOATS;

#pragma unroll
        for (int kk = 0; kk < 4; kk++) {
            const int kc = kk * 8 + t4;
            uint32_t a[4][4], b[4][2];
#pragma unroll
            for (int mt = 0; mt < 4; mt++) {
                const int r0 = wm * 64 + mt * 16 + g;
                a[mt][0] = As[(r0    ) * LDR + kc    ];
                a[mt][1] = As[(r0 + 8) * LDR + kc    ];
                a[mt][2] = As[(r0    ) * LDR + kc + 4];
                a[mt][3] = As[(r0 + 8) * LDR + kc + 4];
            }
#pragma unroll
            for (int nt = 0; nt < 4; nt++) {
                const int r0 = wn * 32 + nt * 8 + g;
                b[nt][0] = Bs[r0 * LDR + kc    ];
                b[nt][1] = Bs[r0 * LDR + kc + 4];
            }
#pragma unroll
            for (int mt = 0; mt < 4; mt++)
#pragma unroll
                for (int nt = 0; nt < 4; nt++)
                    mma_tf32(acc[mt][nt][0], acc[mt][nt][1], acc[mt][nt][2], acc[mt][nt][3],
                             a[mt][0], a[mt][1], a[mt][2], a[mt][3],
                             b[nt][0], b[nt][1]);
        }
        __syncthreads();
        if (kt + 2 < KT) { load_stage(kt & 1, kt + 2); CP_COMMIT(); }
    }

    // Epilogue: c0,c1 -> (row g, cols 2*t4, 2*t4+1); c2,c3 -> row g+8.
#pragma unroll
    for (int mt = 0; mt < 4; mt++) {
        const int mr = m0 + wm * 64 + mt * 16 + g;
#pragma unroll
        for (int nt = 0; nt < 4; nt++) {
            const int nc = n0 + wn * 32 + nt * 8 + 2 * t4;
            float f0 = acc[mt][nt][0], f1 = acc[mt][nt][1];
            float f2 = acc[mt][nt][2], f3 = acc[mt][nt][3];
            if (BIAS) {
                float b0 = __ldg(bias + nc), b1 = __ldg(bias + nc + 1);
                f0 += b0; f1 += b1; f2 += b0; f3 += b1;
            }
            if (SCALE) { f0 *= scale; f1 *= scale; f2 *= scale; f3 *= scale; }
            if (ROUND) {
                f0 = rna_tf32(f0); f1 = rna_tf32(f1);
                f2 = rna_tf32(f2); f3 = rna_tf32(f3);
            }
            float2 v0 = make_float2(f0, f1);
            float2 v1 = make_float2(f2, f3);
            *(float2*)(C + (size_t)mr * N + nc)       = v0;
            *(float2*)(C + (size_t)(mr + 8) * N + nc) = v1;
        }
    }
}

// ---------------------------------------------------------------------------
// Elementwise tf32 round (x -> xr)
// ---------------------------------------------------------------------------
__global__ void round_tf32_kernel(const float* __restrict__ src, float* __restrict__ dst, int n4)
{
    int i = blockIdx.x * blockDim.x + threadIdx.x;
    if (i >= n4) return;
    float4 v = ((const float4*)src)[i];
    v.x = rna_tf32(v.x); v.y = rna_tf32(v.y); v.z = rna_tf32(v.z); v.w = rna_tf32(v.w);
    ((float4*)dst)[i] = v;
}

// ---------------------------------------------------------------------------
// Transpose + tf32 round: dst[c, r] = rna(src[r, c]); batched via blockIdx.z
// ---------------------------------------------------------------------------
__global__ void transpose_round(const float* __restrict__ src, float* __restrict__ dst,
                                int R, int Ccols, size_t sSrc, size_t sDst)
{
    src += (size_t)blockIdx.z * sSrc;
    dst += (size_t)blockIdx.z * sDst;
    __shared__ float t[32][33];
    const int r0 = blockIdx.y * 32, c0 = blockIdx.x * 32;
#pragma unroll
    for (int i = 0; i < 4; i++) {
        int r = r0 + threadIdx.y + i * 8;
        t[threadIdx.y + i * 8][threadIdx.x] = src[(size_t)r * Ccols + c0 + threadIdx.x];
    }
    __syncthreads();
#pragma unroll
    for (int i = 0; i < 4; i++) {
        int c = c0 + threadIdx.y + i * 8;
        dst[(size_t)c * R + r0 + threadIdx.x] = rna_tf32(t[threadIdx.x][threadIdx.y + i * 8]);
    }
}

// ---------------------------------------------------------------------------
// Causal softmax in place; stores tf32-rounded probs, zero-fills masked tail.
// ---------------------------------------------------------------------------
__global__ __launch_bounds__(256) void softmax_causal(float* __restrict__ S)
{
    const int t = blockIdx.x;
    const int b = blockIdx.y;
    float* row = S + ((size_t)b * T_ + t) * T_;
    const int L = t + 1;
    const int tid = threadIdx.x;

    __shared__ float buf[T_];
    __shared__ float red[256];

    float mx = -1e30f;
    for (int s = tid; s < L; s += 256) {
        float v = row[s];
        buf[s] = v;
        mx = fmaxf(mx, v);
    }
    red[tid] = mx;
    __syncthreads();
    for (int off = 128; off > 0; off >>= 1) {
        if (tid < off) red[tid] = fmaxf(red[tid], red[tid + off]);
        __syncthreads();
    }
    const float m = red[0];
    __syncthreads();

    float sum = 0.f;
    for (int s = tid; s < L; s += 256) {
        float e = __expf(buf[s] - m);
        buf[s] = e;
        sum += e;
    }
    red[tid] = sum;
    __syncthreads();
    for (int off = 128; off > 0; off >>= 1) {
        if (tid < off) red[tid] += red[tid + off];
        __syncthreads();
    }
    const float inv = 1.0f / red[0];
    __syncthreads();

    for (int s = tid; s < L; s += 256) row[s] = rna_tf32(buf[s] * inv);
    for (int s = L + tid; s < T_; s += 256) row[s] = 0.f;
}

// ---------------------------------------------------------------------------
extern "C" void kernel_launch(void* const* d_in, const int* in_sizes, int n_in,
                              void* d_out, int out_size)
{
    const float* x  = (const float*)d_in[0];
    const float* Wq = (const float*)d_in[1];
    const float* bq = (const float*)d_in[2];
    const float* Wk = (const float*)d_in[3];
    const float* bk = (const float*)d_in[4];
    const float* Wv = (const float*)d_in[5];
    const float* bv = (const float*)d_in[6];
    float* out = (float*)d_out;

    float *xr, *wt, *q, *k, *v, *vt, *s;
    cudaGetSymbolAddress((void**)&xr, g_xr);
    cudaGetSymbolAddress((void**)&wt, g_wt);
    cudaGetSymbolAddress((void**)&q,  g_q);
    cudaGetSymbolAddress((void**)&k,  g_k);
    cudaGetSymbolAddress((void**)&v,  g_v);
    cudaGetSymbolAddress((void**)&vt, g_vt);
    cudaGetSymbolAddress((void**)&s,  g_s);
    float* wqT = wt;
    float* wkT = wt + (size_t)D_ * D_;
    float* wvT = wt + 2 * (size_t)D_ * D_;

    cudaFuncSetAttribute(gemm_tc<true,  false, false, false, true >, cudaFuncAttributeMaxDynamicSharedMemorySize, SMEM_BYTES);
    cudaFuncSetAttribute(gemm_tc<true,  false, false, false, false>, cudaFuncAttributeMaxDynamicSharedMemorySize, SMEM_BYTES);
    cudaFuncSetAttribute(gemm_tc<false, true,  true,  false, false>, cudaFuncAttributeMaxDynamicSharedMemorySize, SMEM_BYTES);
    cudaFuncSetAttribute(gemm_tc<false, false, false, true,  false>, cudaFuncAttributeMaxDynamicSharedMemorySize, SMEM_BYTES);

    const int M = B_ * T_;               // 8192
    const size_t TD = (size_t)T_ * D_;
    const size_t TT = (size_t)T_ * T_;

    // 0) pre-round x; transpose+round W
    round_tf32_kernel<<<(M * D_ / 4 + 255) / 256, 256>>>(x, xr, M * D_ / 4);
    dim3 gW(D_ / 32, D_ / 32, 1);
    transpose_round<<<gW, dim3(32, 8)>>>(Wq, wqT, D_, D_, 0, 0);
    transpose_round<<<gW, dim3(32, 8)>>>(Wk, wkT, D_, D_, 0, 0);
    transpose_round<<<gW, dim3(32, 8)>>>(Wv, wvT, D_, D_, 0, 0);

    // 1) projections: q/k rounded in epilogue, v stays fp32 (rounded in transpose)
    dim3 gProj(D_ / BN, M / BM, 1);
    gemm_tc<true, false, false, false, true ><<<gProj, 256, SMEM_BYTES>>>(xr, wqT, bq, q, M, D_, D_, 1.f, 0, 0, 0);
    gemm_tc<true, false, false, false, true ><<<gProj, 256, SMEM_BYTES>>>(xr, wkT, bk, k, M, D_, D_, 1.f, 0, 0, 0);
    gemm_tc<true, false, false, false, false><<<gProj, 256, SMEM_BYTES>>>(xr, wvT, bv, v, M, D_, D_, 1.f, 0, 0, 0);

    // 2) v^T (per batch), tf32-rounded
    transpose_round<<<dim3(D_ / 32, T_ / 32, B_), dim3(32, 8)>>>(v, vt, T_, D_, TD, TD);

    // 3) S = Q K^T / 32 (lower-triangle tiles only)
    dim3 gS(T_ / BN, T_ / BM, B_);
    gemm_tc<false, true, true, false, false><<<gS, 256, SMEM_BYTES>>>(q, k, nullptr, s, T_, T_, D_, 1.0f / 32.0f, TD, TD, TT);

    // 4) causal softmax (rounds P, zero-fills tail)
    softmax_causal<<<dim3(T_, B_), 256>>>(s);

    // 5) out = P @ (V^T)^T with causal K-limit
    dim3 gPV(D_ / BN, T_ / BM, B_);
    gemm_tc<false, false, false, true, false><<<gPV, 256, SMEM_BYTES>>>(s, vt, nullptr, out, T_, D_, T_, 1.f, TT, TD, TD);
}

// round 4
// speedup vs baseline: 5.7969x; 1.0809x over previous
#include <cuda_runtime.h>
#include <cuda_bf16.h>
#include <cstdint>
#include <cstddef>

#define B_ 4
#define T_ 2048
#define D_ 1024

// ---------------------------------------------------------------------------
// Scratch (__device__ globals: allocation-free rule)
// ---------------------------------------------------------------------------
__device__ float g_xr[(size_t)B_ * T_ * D_];            // x rounded to tf32
__device__ float g_wt[3][(size_t)D_ * D_];              // W^T rounded (q,k,v)
__device__ float g_qkv[3][(size_t)B_ * T_ * D_];        // q,k,v outputs
__device__ float g_vt[(size_t)B_ * D_ * T_];            // v^T (tf32-rounded)
__device__ float g_s [(size_t)B_ * T_ * T_];            // scores / probs

__device__ __forceinline__ float rna_tf32(float x) {
    uint32_t u;
    asm("cvt.rna.tf32.f32 %0, %1;" : "=r"(u) : "f"(x));
    return __uint_as_float(u);
}

#define CP_ASYNC16(dst, src) \
    asm volatile("cp.async.cg.shared.global [%0], [%1], 16;" :: "r"(dst), "l"(src) : "memory")
#define CP_COMMIT()  asm volatile("cp.async.commit_group;" ::: "memory")
#define CP_WAIT1()   asm volatile("cp.async.wait_group 1;" ::: "memory")
#define CP_WAIT0()   asm volatile("cp.async.wait_group 0;" ::: "memory")

__device__ __forceinline__ uint32_t smem_u32(const void* p) {
    uint32_t a;
    asm("{ .reg .u64 t; cvta.to.shared.u64 t, %1; cvt.u32.u64 %0, t; }" : "=r"(a) : "l"(p));
    return a;
}

// m16n8k8 tf32 mma: D = A@B + D (fp32 accum). a: 4 regs, b: 2 regs, c: 4 regs.
__device__ __forceinline__ void mma_tf32(
    float& c0, float& c1, float& c2, float& c3,
    uint32_t a0, uint32_t a1, uint32_t a2, uint32_t a3,
    uint32_t b0, uint32_t b1)
{
    asm volatile(
        "mma.sync.aligned.m16n8k8.row.col.f32.tf32.tf32.f32 "
        "{%0,%1,%2,%3}, {%4,%5,%6,%7}, {%8,%9}, {%0,%1,%2,%3};"
        : "+f"(c0), "+f"(c1), "+f"(c2), "+f"(c3)
        : "r"(a0), "r"(a1), "r"(a2), "r"(a3), "r"(b0), "r"(b1));
}

// ---------------------------------------------------------------------------
// tf32 tensor GEMM: C[M,N] = A[M,K] @ Bm[N,K]^T (both row-major, K-major tiles)
// 128x128x32 block tile, 8 warps (2m x 4n), 64x32 warp tiles.
// 3-stage cp.async pipeline, one __syncthreads per K-iter.
// QKV3: blockIdx.z selects {Wq,Wk,Wv} / {bq,bk,bv} / {q,k,v} (A shared).
// Otherwise blockIdx.z = batch with strides sA/sB/sC.
// ---------------------------------------------------------------------------
constexpr int BM = 128, BN = 128, BK = 32;
constexpr int LDR = 36;                       // floats per smem row (pad 32->36)
constexpr int TILE_FLOATS = BM * LDR;         // 4608 per operand
constexpr int STAGE_FLOATS = 2 * TILE_FLOATS; // A + B
constexpr int NSTAGE = 3;
constexpr int SMEM_BYTES = NSTAGE * STAGE_FLOATS * 4;   // 110592

template <bool QKV3, bool BIAS, bool SCALE, bool CSKIP, bool KLIM, bool ROUND>
__global__ __launch_bounds__(256, 2) void gemm_tc(
    const float* __restrict__ A, const float* __restrict__ Bm,
    const float* __restrict__ bias0, const float* __restrict__ bias1,
    const float* __restrict__ bias2, float* __restrict__ C,
    int M, int N, int K, float scale, size_t sA, size_t sB, size_t sC)
{
    const int m0 = blockIdx.y * BM;
    const int n0 = blockIdx.x * BN;
    if (CSKIP && n0 >= m0 + BM) return;       // fully above causal diagonal

    const int z = blockIdx.z;
    A  += QKV3 ? 0 : (size_t)z * sA;
    Bm += (size_t)z * sB;
    C  += (size_t)z * sC;
    const float* bias = bias0;
    if (QKV3) bias = (z == 0) ? bias0 : (z == 1) ? bias1 : bias2;

    int Keff = K;
    if (KLIM) { int lim = m0 + BM; Keff = lim < K ? lim : K; }
    const int KT = Keff / BK;

    extern __shared__ float sm[];
    const uint32_t sm_b = smem_u32(sm);

    const int tid = threadIdx.x;
    const int wid = tid >> 5;
    const int lid = tid & 31;
    const int wm = wid >> 2;                  // 0..1
    const int wn = wid & 3;                   // 0..3
    const int g  = lid >> 2;                  // 0..7
    const int t4 = lid & 3;                   // 0..3

    // Stage loader: A tile 128x32 + B tile 128x32, 16B chunks, 8 per thread.
    auto load_stage = [&](int stage, int kt) {
        const uint32_t ab = sm_b + stage * STAGE_FLOATS * 4;
        const uint32_t bb = ab + TILE_FLOATS * 4;
        const float* Ag = A + (size_t)m0 * K + kt * BK;
        const float* Bg = Bm + (size_t)n0 * K + kt * BK;
#pragma unroll
        for (int i = 0; i < 4; i++) {
            int idx = i * 256 + tid;          // 0..1023
            int row = idx >> 3, c = idx & 7;
            uint32_t off = (uint32_t)(row * LDR + c * 4) * 4;
            CP_ASYNC16(ab + off, Ag + (size_t)row * K + c * 4);
            CP_ASYNC16(bb + off, Bg + (size_t)row * K + c * 4);
        }
    };

    load_stage(0, 0);
    CP_COMMIT();
    if (KT > 1) { load_stage(1, 1); CP_COMMIT(); }

    float acc[4][4][4];
#pragma unroll
    for (int i = 0; i < 4; i++)
#pragma unroll
        for (int j = 0; j < 4; j++)
#pragma unroll
            for (int r = 0; r < 4; r++) acc[i][j][r] = 0.f;

    int stage = 0;
    for (int kt = 0; kt < KT; kt++) {
        if (kt + 1 < KT) CP_WAIT1(); else CP_WAIT0();
        __syncthreads();

        // Prefetch stage kt+2 right away (writes a buffer all warps are done with).
        if (kt + 2 < KT) {
            int ns = stage + 2; if (ns >= NSTAGE) ns -= NSTAGE;
            load_stage(ns, kt + 2);
            CP_COMMIT();
        }

        const uint32_t* As = (const uint32_t*)(sm + stage * STAGE_FLOATS);
        const uint32_t* Bs = As + TILE_FLOATS;

#pragma unroll
        for (int kk = 0; kk < 4; kk++) {
            const int kc = kk * 8 + t4;
            uint32_t a[4][4], b[4][2];
#pragma unroll
            for (int mt = 0; mt < 4; mt++) {
                const int r0 = wm * 64 + mt * 16 + g;
                a[mt][0] = As[(r0    ) * LDR + kc    ];
                a[mt][1] = As[(r0 + 8) * LDR + kc    ];
                a[mt][2] = As[(r0    ) * LDR + kc + 4];
                a[mt][3] = As[(r0 + 8) * LDR + kc + 4];
            }
#pragma unroll
            for (int nt = 0; nt < 4; nt++) {
                const int r0 = wn * 32 + nt * 8 + g;
                b[nt][0] = Bs[r0 * LDR + kc    ];
                b[nt][1] = Bs[r0 * LDR + kc + 4];
            }
#pragma unroll
            for (int mt = 0; mt < 4; mt++)
#pragma unroll
                for (int nt = 0; nt < 4; nt++)
                    mma_tf32(acc[mt][nt][0], acc[mt][nt][1], acc[mt][nt][2], acc[mt][nt][3],
                             a[mt][0], a[mt][1], a[mt][2], a[mt][3],
                             b[nt][0], b[nt][1]);
        }
        stage++; if (stage >= NSTAGE) stage = 0;
    }

    // Epilogue: c0,c1 -> (row g, cols 2*t4, 2*t4+1); c2,c3 -> row g+8.
#pragma unroll
    for (int mt = 0; mt < 4; mt++) {
        const int mr = m0 + wm * 64 + mt * 16 + g;
#pragma unroll
        for (int nt = 0; nt < 4; nt++) {
            const int nc = n0 + wn * 32 + nt * 8 + 2 * t4;
            float f0 = acc[mt][nt][0], f1 = acc[mt][nt][1];
            float f2 = acc[mt][nt][2], f3 = acc[mt][nt][3];
            if (BIAS) {
                float b0 = __ldg(bias + nc), b1 = __ldg(bias + nc + 1);
                f0 += b0; f1 += b1; f2 += b0; f3 += b1;
            }
            if (SCALE) { f0 *= scale; f1 *= scale; f2 *= scale; f3 *= scale; }
            if (ROUND) {
                f0 = rna_tf32(f0); f1 = rna_tf32(f1);
                f2 = rna_tf32(f2); f3 = rna_tf32(f3);
            }
            float2 v0 = make_float2(f0, f1);
            float2 v1 = make_float2(f2, f3);
            *(float2*)(C + (size_t)mr * N + nc)       = v0;
            *(float2*)(C + (size_t)(mr + 8) * N + nc) = v1;
        }
    }
}

// ---------------------------------------------------------------------------
// Elementwise tf32 round (x -> xr)
// ---------------------------------------------------------------------------
__global__ void round_tf32_kernel(const float* __restrict__ src, float* __restrict__ dst, int n4)
{
    int i = blockIdx.x * blockDim.x + threadIdx.x;
    if (i >= n4) return;
    float4 v = ((const float4*)src)[i];
    v.x = rna_tf32(v.x); v.y = rna_tf32(v.y); v.z = rna_tf32(v.z); v.w = rna_tf32(v.w);
    ((float4*)dst)[i] = v;
}

// ---------------------------------------------------------------------------
// Transpose + tf32 round: dst[c, r] = rna(src[r, c]); batched via blockIdx.z
// Also used to transpose the three W matrices in one launch (sSrc/sDst strides).
// ---------------------------------------------------------------------------
__global__ void transpose_round(const float* __restrict__ src, float* __restrict__ dst,
                                int R, int Ccols, size_t sSrc, size_t sDst)
{
    src += (size_t)blockIdx.z * sSrc;
    dst += (size_t)blockIdx.z * sDst;
    __shared__ float t[32][33];
    const int r0 = blockIdx.y * 32, c0 = blockIdx.x * 32;
#pragma unroll
    for (int i = 0; i < 4; i++) {
        int r = r0 + threadIdx.y + i * 8;
        t[threadIdx.y + i * 8][threadIdx.x] = src[(size_t)r * Ccols + c0 + threadIdx.x];
    }
    __syncthreads();
#pragma unroll
    for (int i = 0; i < 4; i++) {
        int c = c0 + threadIdx.y + i * 8;
        dst[(size_t)c * R + r0 + threadIdx.x] = rna_tf32(t[threadIdx.x][threadIdx.y + i * 8]);
    }
}

// ---------------------------------------------------------------------------
// Causal softmax in place; stores tf32-rounded probs, zero-fills masked tail.
// ---------------------------------------------------------------------------
__global__ __launch_bounds__(256) void softmax_causal(float* __restrict__ S)
{
    const int t = blockIdx.x;
    const int b = blockIdx.y;
    float* row = S + ((size_t)b * T_ + t) * T_;
    const int L = t + 1;
    const int tid = threadIdx.x;

    __shared__ float buf[T_];
    __shared__ float red[256];

    float mx = -1e30f;
    for (int s = tid; s < L; s += 256) {
        float v = row[s];
        buf[s] = v;
        mx = fmaxf(mx, v);
    }
    red[tid] = mx;
    __syncthreads();
    for (int off = 128; off > 0; off >>= 1) {
        if (tid < off) red[tid] = fmaxf(red[tid], red[tid + off]);
        __syncthreads();
    }
    const float m = red[0];
    __syncthreads();

    float sum = 0.f;
    for (int s = tid; s < L; s += 256) {
        float e = __expf(buf[s] - m);
        buf[s] = e;
        sum += e;
    }
    red[tid] = sum;
    __syncthreads();
    for (int off = 128; off > 0; off >>= 1) {
        if (tid < off) red[tid] += red[tid + off];
        __syncthreads();
    }
    const float inv = 1.0f / red[0];
    __syncthreads();

    for (int s = tid; s < L; s += 256) row[s] = rna_tf32(buf[s] * inv);
    for (int s = L + tid; s < T_; s += 256) row[s] = 0.f;
}

// ---------------------------------------------------------------------------
extern "C" void kernel_launch(void* const* d_in, const int* in_sizes, int n_in,
                              void* d_out, int out_size)
{
    const float* x  = (const float*)d_in[0];
    const float* Wq = (const float*)d_in[1];
    const float* bq = (const float*)d_in[2];
    const float* Wk = (const float*)d_in[3];
    const float* bk = (const float*)d_in[4];
    const float* Wv = (const float*)d_in[5];
    const float* bv = (const float*)d_in[6];
    float* out = (float*)d_out;

    float *xr, *wt, *qkv, *vt, *s;
    cudaGetSymbolAddress((void**)&xr,  g_xr);
    cudaGetSymbolAddress((void**)&wt,  g_wt);
    cudaGetSymbolAddress((void**)&qkv, g_qkv);
    cudaGetSymbolAddress((void**)&vt,  g_vt);
    cudaGetSymbolAddress((void**)&s,   g_s);

    const int M = B_ * T_;               // 8192
    const size_t TD = (size_t)T_ * D_;
    const size_t TT = (size_t)T_ * T_;
    const size_t DD = (size_t)D_ * D_;
    float* q = qkv;
    float* k = qkv + (size_t)M * D_;
    float* v = qkv + 2 * (size_t)M * D_;

    cudaFuncSetAttribute(gemm_tc<true,  true,  false, false, false, true >, cudaFuncAttributeMaxDynamicSharedMemorySize, SMEM_BYTES);
    cudaFuncSetAttribute(gemm_tc<false, false, true,  true,  false, false>, cudaFuncAttributeMaxDynamicSharedMemorySize, SMEM_BYTES);
    cudaFuncSetAttribute(gemm_tc<false, false, false, false, true,  false>, cudaFuncAttributeMaxDynamicSharedMemorySize, SMEM_BYTES);

    // 0) pre-round x; transpose+round all W in one launch (they're not
    //    contiguous inputs, so W transposes use per-matrix launches z=1 via
    //    pointer math — keep 3 small launches, they're ~2us each)
    round_tf32_kernel<<<(M * D_ / 4 + 255) / 256, 256>>>(x, xr, M * D_ / 4);
    dim3 gW(D_ / 32, D_ / 32, 1);
    transpose_round<<<gW, dim3(32, 8)>>>(Wq, wt,           D_, D_, 0, 0);
    transpose_round<<<gW, dim3(32, 8)>>>(Wk, wt + DD,      D_, D_, 0, 0);
    transpose_round<<<gW, dim3(32, 8)>>>(Wv, wt + 2 * DD,  D_, D_, 0, 0);

    // 1) fused QKV projections: one launch, grid.z selects q/k/v
    dim3 gProj(D_ / BN, M / BM, 3);
    gemm_tc<true, true, false, false, false, true><<<gProj, 256, SMEM_BYTES>>>(
        xr, wt, bq, bk, bv, qkv, M, D_, D_, 1.f, 0, DD, (size_t)M * D_);

    // 2) v^T (per batch), tf32-rounded
    transpose_round<<<dim3(D_ / 32, T_ / 32, B_), dim3(32, 8)>>>(v, vt, T_, D_, TD, TD);

    // 3) S = Q K^T / 32 (lower-triangle tiles only)
    dim3 gS(T_ / BN, T_ / BM, B_);
    gemm_tc<false, false, true, true, false, false><<<gS, 256, SMEM_BYTES>>>(
        q, k, nullptr, nullptr, nullptr, s, T_, T_, D_, 1.0f / 32.0f, TD, TD, TT);

    // 4) causal softmax (rounds P, zero-fills tail)
    softmax_causal<<<dim3(T_, B_), 256>>>(s);

    // 5) out = P @ (V^T)^T with causal K-limit
    dim3 gPV(D_ / BN, T_ / BM, B_);
    gemm_tc<false, false, false, false, true, false><<<gPV, 256, SMEM_BYTES>>>(
        s, vt, nullptr, nullptr, nullptr, out, T_, D_, T_, 1.f, TT, TD, TD);
}

// round 6
// speedup vs baseline: 9.7748x; 1.6862x over previous
#include <cuda_runtime.h>
#include <cuda_fp16.h>
#include <cstdint>
#include <cstddef>

#define B_ 4
#define T_ 2048
#define D_ 1024

// ---------------------------------------------------------------------------
// Scratch (__device__ globals: allocation-free rule)
// ---------------------------------------------------------------------------
__device__ __half g_xh[(size_t)B_ * T_ * D_];           // x in fp16
__device__ __half g_wt[3][(size_t)D_ * D_];             // W^T fp16 (q,k,v)
__device__ __half g_qkv[3][(size_t)B_ * T_ * D_];       // q,k,v fp16
__device__ __half g_vt[(size_t)B_ * D_ * T_];           // v^T fp16
__device__ float  g_s [(size_t)B_ * T_ * T_];           // scores fp32
__device__ __half g_p [(size_t)B_ * T_ * T_];           // probs fp16

#define CP_ASYNC16(dst, src) \
    asm volatile("cp.async.cg.shared.global [%0], [%1], 16;" :: "r"(dst), "l"(src) : "memory")
#define CP_COMMIT()  asm volatile("cp.async.commit_group;" ::: "memory")
#define CP_WAIT1()   asm volatile("cp.async.wait_group 1;" ::: "memory")
#define CP_WAIT0()   asm volatile("cp.async.wait_group 0;" ::: "memory")

__device__ __forceinline__ uint32_t smem_u32(const void* p) {
    uint32_t a;
    asm("{ .reg .u64 t; cvta.to.shared.u64 t, %1; cvt.u32.u64 %0, t; }" : "=r"(a) : "l"(p));
    return a;
}

#define LDSM_X4(r0, r1, r2, r3, addr)                                        \
    asm volatile("ldmatrix.sync.aligned.m8n8.x4.shared.b16 {%0,%1,%2,%3}, [%4];" \
        : "=r"(r0), "=r"(r1), "=r"(r2), "=r"(r3) : "r"(addr))

// m16n8k16 fp16 mma, fp32 accum
__device__ __forceinline__ void mma_f16(
    float& c0, float& c1, float& c2, float& c3,
    uint32_t a0, uint32_t a1, uint32_t a2, uint32_t a3,
    uint32_t b0, uint32_t b1)
{
    asm volatile(
        "mma.sync.aligned.m16n8k16.row.col.f32.f16.f16.f32 "
        "{%0,%1,%2,%3}, {%4,%5,%6,%7}, {%8,%9}, {%0,%1,%2,%3};"
        : "+f"(c0), "+f"(c1), "+f"(c2), "+f"(c3)
        : "r"(a0), "r"(a1), "r"(a2), "r"(a3), "r"(b0), "r"(b1));
}

// ---------------------------------------------------------------------------
// fp16 tensor GEMM: C[M,N] = A[M,K] @ Bm[N,K]^T (half, K-major rows)
// 128x128x64 block tile, 8 warps (2m x 4n) -> 64x32 warp tiles.
// smem rows padded to 72 halves (144B: stride 9*16B -> conflict-free LDSM).
// 3-stage cp.async pipeline. OUTH: write half, else float.
// ---------------------------------------------------------------------------
constexpr int BM = 128, BN = 128, BK = 64;
constexpr int LDH = 72;                        // halves per smem row
constexpr int TILE_BYTES  = BM * LDH * 2;      // 18432
constexpr int STAGE_BYTES = 2 * TILE_BYTES;    // 36864 (A + B)
constexpr int NSTAGE = 3;
constexpr int SMEM_BYTES = NSTAGE * STAGE_BYTES;  // 110592

template <bool QKV3, bool BIAS, bool SCALE, bool CSKIP, bool KLIM, bool OUTH>
__global__ __launch_bounds__(256, 2) void gemm_h(
    const __half* __restrict__ A, const __half* __restrict__ Bm,
    const float* __restrict__ bias0, const float* __restrict__ bias1,
    const float* __restrict__ bias2, void* __restrict__ Cv,
    int M, int N, int K, float scale, size_t sA, size_t sB, size_t sC)
{
    const int m0 = blockIdx.y * BM;
    const int n0 = blockIdx.x * BN;
    if (CSKIP && n0 >= m0 + BM) return;        // fully above causal diagonal

    const int z = blockIdx.z;
    A  += QKV3 ? 0 : (size_t)z * sA;
    Bm += (size_t)z * sB;
    const float* bias = bias0;
    if (QKV3) bias = (z == 0) ? bias0 : (z == 1) ? bias1 : bias2;

    int Keff = K;
    if (KLIM) { int lim = m0 + BM; Keff = lim < K ? lim : K; }
    const int KT = Keff / BK;

    extern __shared__ char sm[];
    const uint32_t sm_b = smem_u32(sm);

    const int tid = threadIdx.x;
    const int wid = tid >> 5;
    const int lid = tid & 31;
    const int wm = wid >> 2;                   // 0..1
    const int wn = wid & 3;                    // 0..3
    const int g  = lid >> 2;                   // 0..7
    const int t4 = lid & 3;                    // 0..3

    // Stage loader: A tile 128x64h + B tile 128x64h; 16B chunks, 8/thread each
    auto load_stage = [&](int stage, int kt) {
        const uint32_t ab = sm_b + stage * STAGE_BYTES;
        const uint32_t bb = ab + TILE_BYTES;
        const __half* Ag = A + (size_t)m0 * K + kt * BK;
        const __half* Bg = Bm + (size_t)n0 * K + kt * BK;
#pragma unroll
        for (int i = 0; i < 4; i++) {
            int idx = i * 256 + tid;           // 0..1023
            int row = idx >> 3, c = idx & 7;
            uint32_t off = (uint32_t)(row * 144 + c * 16);
            CP_ASYNC16(ab + off, Ag + (size_t)row * K + c * 8);
            CP_ASYNC16(bb + off, Bg + (size_t)row * K + c * 8);
        }
    };

    load_stage(0, 0);
    CP_COMMIT();
    if (KT > 1) { load_stage(1, 1); CP_COMMIT(); }

    // LDSM per-lane address pieces: lanes 0-15 -> rows +0..15, lanes 16-31 add
    // 16B (k+8 halves).
    const int lrow = lid & 15;
    const uint32_t lk = (lid & 16) ? 16u : 0u;
    const uint32_t aoff = (uint32_t)((wm * 64 + lrow) * 144) + lk;
    const uint32_t boff = (uint32_t)((wn * 32 + lrow) * 144) + lk;

    float acc[4][4][4];
#pragma unroll
    for (int i = 0; i < 4; i++)
#pragma unroll
        for (int j = 0; j < 4; j++)
#pragma unroll
            for (int r = 0; r < 4; r++) acc[i][j][r] = 0.f;

    int stage = 0;
    for (int kt = 0; kt < KT; kt++) {
        if (kt + 1 < KT) CP_WAIT1(); else CP_WAIT0();
        __syncthreads();

        if (kt + 2 < KT) {
            int ns = stage + 2; if (ns >= NSTAGE) ns -= NSTAGE;
            load_stage(ns, kt + 2);
            CP_COMMIT();
        }

        const uint32_t Ab = sm_b + stage * STAGE_BYTES;
        const uint32_t Bb = Ab + TILE_BYTES;

#pragma unroll
        for (int s = 0; s < 4; s++) {          // 4 x k16 steps
            uint32_t a[4][4], bb[2][4];
#pragma unroll
            for (int mt = 0; mt < 4; mt++)
                LDSM_X4(a[mt][0], a[mt][1], a[mt][2], a[mt][3],
                        Ab + aoff + mt * (16 * 144) + s * 32);
#pragma unroll
            for (int p = 0; p < 2; p++)
                LDSM_X4(bb[p][0], bb[p][1], bb[p][2], bb[p][3],
                        Bb + boff + p * (16 * 144) + s * 32);
#pragma unroll
            for (int mt = 0; mt < 4; mt++)
#pragma unroll
                for (int nt = 0; nt < 4; nt++) {
                    const int p = nt >> 1, o = nt & 1;
                    mma_f16(acc[mt][nt][0], acc[mt][nt][1],
                            acc[mt][nt][2], acc[mt][nt][3],
                            a[mt][0], a[mt][1], a[mt][2], a[mt][3],
                            bb[p][o], bb[p][2 + o]);
                }
        }
        stage++; if (stage >= NSTAGE) stage = 0;
    }

    // Epilogue: c0,c1 -> (row g, cols 2t4,2t4+1); c2,c3 -> row g+8.
#pragma unroll
    for (int mt = 0; mt < 4; mt++) {
        const int mr = m0 + wm * 64 + mt * 16 + g;
#pragma unroll
        for (int nt = 0; nt < 4; nt++) {
            const int nc = n0 + wn * 32 + nt * 8 + 2 * t4;
            float f0 = acc[mt][nt][0], f1 = acc[mt][nt][1];
            float f2 = acc[mt][nt][2], f3 = acc[mt][nt][3];
            if (BIAS) {
                float b0 = __ldg(bias + nc), b1 = __ldg(bias + nc + 1);
                f0 += b0; f1 += b1; f2 += b0; f3 += b1;
            }
            if (SCALE) { f0 *= scale; f1 *= scale; f2 *= scale; f3 *= scale; }
            if (OUTH) {
                __half* C = (__half*)Cv + (size_t)z * sC;
                *(__half2*)(C + (size_t)mr * N + nc) =
                    __floats2half2_rn(f0, f1);
                *(__half2*)(C + (size_t)(mr + 8) * N + nc) =
                    __floats2half2_rn(f2, f3);
            } else {
                float* C = (float*)Cv + (size_t)z * sC;
                *(float2*)(C + (size_t)mr * N + nc)       = make_float2(f0, f1);
                *(float2*)(C + (size_t)(mr + 8) * N + nc) = make_float2(f2, f3);
            }
        }
    }
}

// ---------------------------------------------------------------------------
// fp32 -> fp16 convert (x)
// ---------------------------------------------------------------------------
__global__ void f2h_kernel(const float* __restrict__ src, __half* __restrict__ dst, int n8)
{
    int i = blockIdx.x * blockDim.x + threadIdx.x;
    if (i >= n8) return;
    float4 v0 = ((const float4*)src)[2 * i];
    float4 v1 = ((const float4*)src)[2 * i + 1];
    __half2 h[4];
    h[0] = __floats2half2_rn(v0.x, v0.y);
    h[1] = __floats2half2_rn(v0.z, v0.w);
    h[2] = __floats2half2_rn(v1.x, v1.y);
    h[3] = __floats2half2_rn(v1.z, v1.w);
    ((uint4*)dst)[i] = *(uint4*)h;
}

// ---------------------------------------------------------------------------
// Transpose fp32 -> fp16: dst[c, r] = (half)src[r, c]
// ---------------------------------------------------------------------------
__global__ void transpose_f2h(const float* __restrict__ src, __half* __restrict__ dst,
                              int R, int Ccols)
{
    __shared__ float t[32][33];
    const int r0 = blockIdx.y * 32, c0 = blockIdx.x * 32;
#pragma unroll
    for (int i = 0; i < 4; i++) {
        int r = r0 + threadIdx.y + i * 8;
        t[threadIdx.y + i * 8][threadIdx.x] = src[(size_t)r * Ccols + c0 + threadIdx.x];
    }
    __syncthreads();
#pragma unroll
    for (int i = 0; i < 4; i++) {
        int c = c0 + threadIdx.y + i * 8;
        dst[(size_t)c * R + r0 + threadIdx.x] =
            __float2half_rn(t[threadIdx.x][threadIdx.y + i * 8]);
    }
}

// ---------------------------------------------------------------------------
// Transpose fp16 -> fp16: dst[c, r] = src[r, c]; batched via blockIdx.z
// ---------------------------------------------------------------------------
__global__ void transpose_h2h(const __half* __restrict__ src, __half* __restrict__ dst,
                              int R, int Ccols, size_t sSrc, size_t sDst)
{
    src += (size_t)blockIdx.z * sSrc;
    dst += (size_t)blockIdx.z * sDst;
    __shared__ __half t[32][34];
    const int r0 = blockIdx.y * 32, c0 = blockIdx.x * 32;
#pragma unroll
    for (int i = 0; i < 4; i++) {
        int r = r0 + threadIdx.y + i * 8;
        t[threadIdx.y + i * 8][threadIdx.x] = src[(size_t)r * Ccols + c0 + threadIdx.x];
    }
    __syncthreads();
#pragma unroll
    for (int i = 0; i < 4; i++) {
        int c = c0 + threadIdx.y + i * 8;
        dst[(size_t)c * R + r0 + threadIdx.x] = t[threadIdx.x][threadIdx.y + i * 8];
    }
}

// ---------------------------------------------------------------------------
// Causal softmax: reads fp32 S, writes fp16 P (zero-fills masked tail).
// ---------------------------------------------------------------------------
__global__ __launch_bounds__(256) void softmax_causal(
    const float* __restrict__ S, __half* __restrict__ P)
{
    const int t = blockIdx.x;
    const int b = blockIdx.y;
    const float* row = S + ((size_t)b * T_ + t) * T_;
    __half* prow = P + ((size_t)b * T_ + t) * T_;
    const int L = t + 1;
    const int tid = threadIdx.x;

    __shared__ float buf[T_];
    __shared__ float red[256];

    float mx = -1e30f;
    for (int s = tid; s < L; s += 256) {
        float v = row[s];
        buf[s] = v;
        mx = fmaxf(mx, v);
    }
    red[tid] = mx;
    __syncthreads();
    for (int off = 128; off > 0; off >>= 1) {
        if (tid < off) red[tid] = fmaxf(red[tid], red[tid + off]);
        __syncthreads();
    }
    const float m = red[0];
    __syncthreads();

    float sum = 0.f;
    for (int s = tid; s < L; s += 256) {
        float e = __expf(buf[s] - m);
        buf[s] = e;
        sum += e;
    }
    red[tid] = sum;
    __syncthreads();
    for (int off = 128; off > 0; off >>= 1) {
        if (tid < off) red[tid] += red[tid + off];
        __syncthreads();
    }
    const float inv = 1.0f / red[0];
    __syncthreads();

    for (int s = tid; s < L; s += 256) prow[s] = __float2half_rn(buf[s] * inv);
    for (int s = L + tid; s < T_; s += 256) prow[s] = __float2half_rn(0.f);
}

// ---------------------------------------------------------------------------
extern "C" void kernel_launch(void* const* d_in, const int* in_sizes, int n_in,
                              void* d_out, int out_size)
{
    const float* x  = (const float*)d_in[0];
    const float* Wq = (const float*)d_in[1];
    const float* bq = (const float*)d_in[2];
    const float* Wk = (const float*)d_in[3];
    const float* bk = (const float*)d_in[4];
    const float* Wv = (const float*)d_in[5];
    const float* bv = (const float*)d_in[6];
    float* out = (float*)d_out;

    __half *xh, *wt, *qkv, *vt, *p;
    float *s;
    cudaGetSymbolAddress((void**)&xh,  g_xh);
    cudaGetSymbolAddress((void**)&wt,  g_wt);
    cudaGetSymbolAddress((void**)&qkv, g_qkv);
    cudaGetSymbolAddress((void**)&vt,  g_vt);
    cudaGetSymbolAddress((void**)&s,   g_s);
    cudaGetSymbolAddress((void**)&p,   g_p);

    const int M = B_ * T_;               // 8192
    const size_t TD = (size_t)T_ * D_;
    const size_t TT = (size_t)T_ * T_;
    const size_t DD = (size_t)D_ * D_;
    __half* q = qkv;
    __half* k = qkv + (size_t)M * D_;
    __half* v = qkv + 2 * (size_t)M * D_;

    cudaFuncSetAttribute(gemm_h<true,  true,  false, false, false, true >, cudaFuncAttributeMaxDynamicSharedMemorySize, SMEM_BYTES);
    cudaFuncSetAttribute(gemm_h<false, false, true,  true,  false, false>, cudaFuncAttributeMaxDynamicSharedMemorySize, SMEM_BYTES);
    cudaFuncSetAttribute(gemm_h<false, false, false, false, true,  false>, cudaFuncAttributeMaxDynamicSharedMemorySize, SMEM_BYTES);

    // 0) x -> fp16; W -> W^T fp16
    f2h_kernel<<<(M * D_ / 8 + 255) / 256, 256>>>(x, xh, M * D_ / 8);
    dim3 gW(D_ / 32, D_ / 32, 1);
    transpose_f2h<<<gW, dim3(32, 8)>>>(Wq, wt,           D_, D_);
    transpose_f2h<<<gW, dim3(32, 8)>>>(Wk, wt + DD,      D_, D_);
    transpose_f2h<<<gW, dim3(32, 8)>>>(Wv, wt + 2 * DD,  D_, D_);

    // 1) fused QKV projections (one launch, z selects q/k/v), fp16 out
    dim3 gProj(D_ / BN, M / BM, 3);
    gemm_h<true, true, false, false, false, true><<<gProj, 256, SMEM_BYTES>>>(
        xh, wt, bq, bk, bv, qkv, M, D_, D_, 1.f, 0, DD, (size_t)M * D_);

    // 2) v^T (per batch), fp16
    transpose_h2h<<<dim3(D_ / 32, T_ / 32, B_), dim3(32, 8)>>>(v, vt, T_, D_, TD, TD);

    // 3) S = Q K^T / 32 (lower-triangle tiles only), fp32 out
    dim3 gS(T_ / BN, T_ / BM, B_);
    gemm_h<false, false, true, true, false, false><<<gS, 256, SMEM_BYTES>>>(
        q, k, nullptr, nullptr, nullptr, s, T_, T_, D_, 1.0f / 32.0f, TD, TD, TT);

    // 4) causal softmax: fp32 S -> fp16 P (zero tail)
    softmax_causal<<<dim3(T_, B_), 256>>>(s, p);

    // 5) out = P @ (V^T)^T with causal K-limit, fp32 out
    dim3 gPV(D_ / BN, T_ / BM, B_);
    gemm_h<false, false, false, false, true, false><<<gPV, 256, SMEM_BYTES>>>(
        p, vt, nullptr, nullptr, nullptr, out, T_, D_, T_, 1.f, TT, TD, TD);
}

// round 7
// speedup vs baseline: 10.8471x; 1.1097x over previous
#include <cuda_runtime.h>
#include <cuda_fp16.h>
#include <cstdint>
#include <cstddef>

#define B_ 4
#define T_ 2048
#define D_ 1024

// ---------------------------------------------------------------------------
// Scratch (__device__ globals: allocation-free rule)
// ---------------------------------------------------------------------------
__device__ __half g_xh[(size_t)B_ * T_ * D_];           // x in fp16
__device__ __half g_wt[3][(size_t)D_ * D_];             // W^T fp16 (q,k,v)
__device__ __half g_qkv[3][(size_t)B_ * T_ * D_];       // q,k,v fp16
__device__ __half g_vt[(size_t)B_ * D_ * T_];           // v^T fp16
__device__ __half g_p [(size_t)B_ * T_ * T_];           // E = exp(S) fp16
__device__ float  g_rs[(size_t)B_ * T_];                // row sums of E

#define CP_ASYNC16(dst, src) \
    asm volatile("cp.async.cg.shared.global [%0], [%1], 16;" :: "r"(dst), "l"(src) : "memory")
#define CP_COMMIT()  asm volatile("cp.async.commit_group;" ::: "memory")
#define CP_WAIT1()   asm volatile("cp.async.wait_group 1;" ::: "memory")
#define CP_WAIT0()   asm volatile("cp.async.wait_group 0;" ::: "memory")

__device__ __forceinline__ uint32_t smem_u32(const void* p) {
    uint32_t a;
    asm("{ .reg .u64 t; cvta.to.shared.u64 t, %1; cvt.u32.u64 %0, t; }" : "=r"(a) : "l"(p));
    return a;
}

#define LDSM_X4(r0, r1, r2, r3, addr)                                        \
    asm volatile("ldmatrix.sync.aligned.m8n8.x4.shared.b16 {%0,%1,%2,%3}, [%4];" \
        : "=r"(r0), "=r"(r1), "=r"(r2), "=r"(r3) : "r"(addr))

// m16n8k16 fp16 mma, fp32 accum
__device__ __forceinline__ void mma_f16(
    float& c0, float& c1, float& c2, float& c3,
    uint32_t a0, uint32_t a1, uint32_t a2, uint32_t a3,
    uint32_t b0, uint32_t b1)
{
    asm volatile(
        "mma.sync.aligned.m16n8k16.row.col.f32.f16.f16.f32 "
        "{%0,%1,%2,%3}, {%4,%5,%6,%7}, {%8,%9}, {%0,%1,%2,%3};"
        : "+f"(c0), "+f"(c1), "+f"(c2), "+f"(c3)
        : "r"(a0), "r"(a1), "r"(a2), "r"(a3), "r"(b0), "r"(b1));
}

// ---------------------------------------------------------------------------
// fp16 tensor GEMM: C[M,N] = A[M,K] @ Bm[N,K]^T (half, K-major rows)
// 128x128x64 block tile, 8 warps (2m x 4n) -> 64x32 warp tiles.
// smem rows padded to 72 halves (144B: 9x16B stride -> conflict-free LDSM).
// 3-stage cp.async pipeline.
// EXPO: epilogue writes fp16 exp(acc*scale) with causal mask on diagonal
//       tiles, accumulating row sums into rs via atomics (QK+softmax-num).
// DIVRS: epilogue divides by rs[row] (PV normalize). KLIM: causal K clip,
//        with heavy-first m-tile order. CSKIP: skip upper-triangle tiles.
// ---------------------------------------------------------------------------
constexpr int BM = 128, BN = 128, BK = 64;
constexpr int LDH = 72;                        // halves per smem row
constexpr int TILE_BYTES  = BM * LDH * 2;      // 18432
constexpr int STAGE_BYTES = 2 * TILE_BYTES;    // 36864 (A + B)
constexpr int NSTAGE = 3;
constexpr int SMEM_BYTES = NSTAGE * STAGE_BYTES;  // 110592

template <bool QKV3, bool BIAS, bool EXPO, bool DIVRS, bool CSKIP, bool KLIM, bool OUTH>
__global__ __launch_bounds__(256, 2) void gemm_h(
    const __half* __restrict__ A, const __half* __restrict__ Bm,
    const float* __restrict__ bias0, const float* __restrict__ bias1,
    const float* __restrict__ bias2, void* __restrict__ Cv,
    float* __restrict__ rs,
    int M, int N, int K, float scale, size_t sA, size_t sB, size_t sC)
{
    const int by = KLIM ? ((int)gridDim.y - 1 - (int)blockIdx.y) : (int)blockIdx.y;
    const int m0 = by * BM;
    const int n0 = blockIdx.x * BN;
    if (CSKIP && n0 >= m0 + BM) return;        // fully above causal diagonal

    const int z = blockIdx.z;
    A  += QKV3 ? 0 : (size_t)z * sA;
    Bm += (size_t)z * sB;
    const float* bias = bias0;
    if (QKV3) bias = (z == 0) ? bias0 : (z == 1) ? bias1 : bias2;

    int Keff = K;
    if (KLIM) { int lim = m0 + BM; Keff = lim < K ? lim : K; }
    const int KT = Keff / BK;

    extern __shared__ char sm[];
    const uint32_t sm_b = smem_u32(sm);

    const int tid = threadIdx.x;
    const int wid = tid >> 5;
    const int lid = tid & 31;
    const int wm = wid >> 2;                   // 0..1
    const int wn = wid & 3;                    // 0..3
    const int g  = lid >> 2;                   // 0..7
    const int t4 = lid & 3;                    // 0..3

    // Stage loader: A tile 128x64h + B tile 128x64h; 16B chunks, 8/thread each
    auto load_stage = [&](int stage, int kt) {
        const uint32_t ab = sm_b + stage * STAGE_BYTES;
        const uint32_t bb = ab + TILE_BYTES;
        const __half* Ag = A + (size_t)m0 * K + kt * BK;
        const __half* Bg = Bm + (size_t)n0 * K + kt * BK;
#pragma unroll
        for (int i = 0; i < 4; i++) {
            int idx = i * 256 + tid;           // 0..1023
            int row = idx >> 3, c = idx & 7;
            uint32_t off = (uint32_t)(row * 144 + c * 16);
            CP_ASYNC16(ab + off, Ag + (size_t)row * K + c * 8);
            CP_ASYNC16(bb + off, Bg + (size_t)row * K + c * 8);
        }
    };

    load_stage(0, 0);
    CP_COMMIT();
    if (KT > 1) { load_stage(1, 1); CP_COMMIT(); }

    // LDSM per-lane address pieces
    const int lrow = lid & 15;
    const uint32_t lk = (lid & 16) ? 16u : 0u;
    const uint32_t aoff = (uint32_t)((wm * 64 + lrow) * 144) + lk;
    const uint32_t boff = (uint32_t)((wn * 32 + lrow) * 144) + lk;

    float acc[4][4][4];
#pragma unroll
    for (int i = 0; i < 4; i++)
#pragma unroll
        for (int j = 0; j < 4; j++)
#pragma unroll
            for (int r = 0; r < 4; r++) acc[i][j][r] = 0.f;

    int stage = 0;
    for (int kt = 0; kt < KT; kt++) {
        if (kt + 1 < KT) CP_WAIT1(); else CP_WAIT0();
        __syncthreads();

        if (kt + 2 < KT) {
            int ns = stage + 2; if (ns >= NSTAGE) ns -= NSTAGE;
            load_stage(ns, kt + 2);
            CP_COMMIT();
        }

        const uint32_t Ab = sm_b + stage * STAGE_BYTES;
        const uint32_t Bb = Ab + TILE_BYTES;

#pragma unroll
        for (int s = 0; s < 4; s++) {          // 4 x k16 steps
            uint32_t a[4][4], bb[2][4];
#pragma unroll
            for (int mt = 0; mt < 4; mt++)
                LDSM_X4(a[mt][0], a[mt][1], a[mt][2], a[mt][3],
                        Ab + aoff + mt * (16 * 144) + s * 32);
#pragma unroll
            for (int p = 0; p < 2; p++)
                LDSM_X4(bb[p][0], bb[p][1], bb[p][2], bb[p][3],
                        Bb + boff + p * (16 * 144) + s * 32);
#pragma unroll
            for (int mt = 0; mt < 4; mt++)
#pragma unroll
                for (int nt = 0; nt < 4; nt++) {
                    const int p = nt >> 1, o = nt & 1;
                    mma_f16(acc[mt][nt][0], acc[mt][nt][1],
                            acc[mt][nt][2], acc[mt][nt][3],
                            a[mt][0], a[mt][1], a[mt][2], a[mt][3],
                            bb[p][o], bb[p][2 + o]);
                }
        }
        stage++; if (stage >= NSTAGE) stage = 0;
    }

    const bool diag = EXPO && (m0 == n0);

    // Epilogue: c0,c1 -> (row g, cols 2t4,2t4+1); c2,c3 -> row g+8.
#pragma unroll
    for (int mt = 0; mt < 4; mt++) {
        const int mr = m0 + wm * 64 + mt * 16 + g;
        float rsum0 = 0.f, rsum1 = 0.f;
        float ia = 1.f, ib = 1.f;
        if (DIVRS) {
            ia = 1.0f / __ldg(rs + (size_t)z * T_ + mr);
            ib = 1.0f / __ldg(rs + (size_t)z * T_ + mr + 8);
        }
#pragma unroll
        for (int nt = 0; nt < 4; nt++) {
            const int nc = n0 + wn * 32 + nt * 8 + 2 * t4;
            float f0 = acc[mt][nt][0], f1 = acc[mt][nt][1];
            float f2 = acc[mt][nt][2], f3 = acc[mt][nt][3];
            if (BIAS) {
                float b0 = __ldg(bias + nc), b1 = __ldg(bias + nc + 1);
                f0 += b0; f1 += b1; f2 += b0; f3 += b1;
            }
            if (EXPO) {
                // E = exp(S * scale), causal mask within diagonal tile.
                float e0 = __expf(f0 * scale), e1 = __expf(f1 * scale);
                float e2 = __expf(f2 * scale), e3 = __expf(f3 * scale);
                if (diag) {
                    if (nc     > mr    ) e0 = 0.f;
                    if (nc + 1 > mr    ) e1 = 0.f;
                    if (nc     > mr + 8) e2 = 0.f;
                    if (nc + 1 > mr + 8) e3 = 0.f;
                }
                __half2 h0 = __floats2half2_rn(e0, e1);
                __half2 h1 = __floats2half2_rn(e2, e3);
                // Sum the fp16-rounded values so rs matches what PV consumes.
                float2 r0 = __half22float2(h0), r1 = __half22float2(h1);
                rsum0 += r0.x + r0.y;
                rsum1 += r1.x + r1.y;
                __half* C = (__half*)Cv + (size_t)z * sC;
                *(__half2*)(C + (size_t)mr * N + nc)       = h0;
                *(__half2*)(C + (size_t)(mr + 8) * N + nc) = h1;
            } else if (OUTH) {
                __half* C = (__half*)Cv + (size_t)z * sC;
                *(__half2*)(C + (size_t)mr * N + nc)       = __floats2half2_rn(f0, f1);
                *(__half2*)(C + (size_t)(mr + 8) * N + nc) = __floats2half2_rn(f2, f3);
            } else {
                if (DIVRS) { f0 *= ia; f1 *= ia; f2 *= ib; f3 *= ib; }
                float* C = (float*)Cv + (size_t)z * sC;
                *(float2*)(C + (size_t)mr * N + nc)       = make_float2(f0, f1);
                *(float2*)(C + (size_t)(mr + 8) * N + nc) = make_float2(f2, f3);
            }
        }
        if (EXPO) {
            // quad-reduce across t4 lanes (same row), then one atomic per row
            rsum0 += __shfl_xor_sync(0xffffffffu, rsum0, 1);
            rsum0 += __shfl_xor_sync(0xffffffffu, rsum0, 2);
            rsum1 += __shfl_xor_sync(0xffffffffu, rsum1, 1);
            rsum1 += __shfl_xor_sync(0xffffffffu, rsum1, 2);
            if (t4 == 0) {
                atomicAdd(rs + (size_t)z * T_ + mr,     rsum0);
                atomicAdd(rs + (size_t)z * T_ + mr + 8, rsum1);
            }
        }
    }
}

// ---------------------------------------------------------------------------
// fp32 -> fp16 convert (x)
// ---------------------------------------------------------------------------
__global__ void f2h_kernel(const float* __restrict__ src, __half* __restrict__ dst, int n8)
{
    int i = blockIdx.x * blockDim.x + threadIdx.x;
    if (i >= n8) return;
    float4 v0 = ((const float4*)src)[2 * i];
    float4 v1 = ((const float4*)src)[2 * i + 1];
    __half2 h[4];
    h[0] = __floats2half2_rn(v0.x, v0.y);
    h[1] = __floats2half2_rn(v0.z, v0.w);
    h[2] = __floats2half2_rn(v1.x, v1.y);
    h[3] = __floats2half2_rn(v1.z, v1.w);
    ((uint4*)dst)[i] = *(uint4*)h;
}

// ---------------------------------------------------------------------------
// Zero the row-sum accumulator
// ---------------------------------------------------------------------------
__global__ void zero_rs_kernel(float* __restrict__ rs, int n)
{
    int i = blockIdx.x * blockDim.x + threadIdx.x;
    if (i < n) rs[i] = 0.f;
}

// ---------------------------------------------------------------------------
// Transpose fp32 -> fp16 for the three weight matrices (z selects q/k/v)
// ---------------------------------------------------------------------------
__global__ void transpose_f2h3(const float* __restrict__ W0, const float* __restrict__ W1,
                               const float* __restrict__ W2, __half* __restrict__ dst,
                               int R, int Ccols, size_t sDst)
{
    const float* src = (blockIdx.z == 0) ? W0 : (blockIdx.z == 1) ? W1 : W2;
    __half* d = dst + (size_t)blockIdx.z * sDst;
    __shared__ float t[32][33];
    const int r0 = blockIdx.y * 32, c0 = blockIdx.x * 32;
#pragma unroll
    for (int i = 0; i < 4; i++) {
        int r = r0 + threadIdx.y + i * 8;
        t[threadIdx.y + i * 8][threadIdx.x] = src[(size_t)r * Ccols + c0 + threadIdx.x];
    }
    __syncthreads();
#pragma unroll
    for (int i = 0; i < 4; i++) {
        int c = c0 + threadIdx.y + i * 8;
        d[(size_t)c * R + r0 + threadIdx.x] =
            __float2half_rn(t[threadIdx.x][threadIdx.y + i * 8]);
    }
}

// ---------------------------------------------------------------------------
// Transpose fp16 -> fp16: dst[c, r] = src[r, c]; batched via blockIdx.z
// ---------------------------------------------------------------------------
__global__ void transpose_h2h(const __half* __restrict__ src, __half* __restrict__ dst,
                              int R, int Ccols, size_t sSrc, size_t sDst)
{
    src += (size_t)blockIdx.z * sSrc;
    dst += (size_t)blockIdx.z * sDst;
    __shared__ __half t[32][34];
    const int r0 = blockIdx.y * 32, c0 = blockIdx.x * 32;
#pragma unroll
    for (int i = 0; i < 4; i++) {
        int r = r0 + threadIdx.y + i * 8;
        t[threadIdx.y + i * 8][threadIdx.x] = src[(size_t)r * Ccols + c0 + threadIdx.x];
    }
    __syncthreads();
#pragma unroll
    for (int i = 0; i < 4; i++) {
        int c = c0 + threadIdx.y + i * 8;
        dst[(size_t)c * R + r0 + threadIdx.x] = t[threadIdx.x][threadIdx.y + i * 8];
    }
}

// ---------------------------------------------------------------------------
extern "C" void kernel_launch(void* const* d_in, const int* in_sizes, int n_in,
                              void* d_out, int out_size)
{
    const float* x  = (const float*)d_in[0];
    const float* Wq = (const float*)d_in[1];
    const float* bq = (const float*)d_in[2];
    const float* Wk = (const float*)d_in[3];
    const float* bk = (const float*)d_in[4];
    const float* Wv = (const float*)d_in[5];
    const float* bv = (const float*)d_in[6];
    float* out = (float*)d_out;

    __half *xh, *wt, *qkv, *vt, *p;
    float *rs;
    cudaGetSymbolAddress((void**)&xh,  g_xh);
    cudaGetSymbolAddress((void**)&wt,  g_wt);
    cudaGetSymbolAddress((void**)&qkv, g_qkv);
    cudaGetSymbolAddress((void**)&vt,  g_vt);
    cudaGetSymbolAddress((void**)&p,   g_p);
    cudaGetSymbolAddress((void**)&rs,  g_rs);

    const int M = B_ * T_;               // 8192
    const size_t TD = (size_t)T_ * D_;
    const size_t TT = (size_t)T_ * T_;
    const size_t DD = (size_t)D_ * D_;
    __half* q = qkv;
    __half* k = qkv + (size_t)M * D_;
    __half* v = qkv + 2 * (size_t)M * D_;

    cudaFuncSetAttribute(gemm_h<true,  true,  false, false, false, false, true >, cudaFuncAttributeMaxDynamicSharedMemorySize, SMEM_BYTES);
    cudaFuncSetAttribute(gemm_h<false, false, true,  false, true,  false, true >, cudaFuncAttributeMaxDynamicSharedMemorySize, SMEM_BYTES);
    cudaFuncSetAttribute(gemm_h<false, false, false, true,  false, true,  false>, cudaFuncAttributeMaxDynamicSharedMemorySize, SMEM_BYTES);

    // 0) x -> fp16; W -> W^T fp16 (single launch); zero rs
    f2h_kernel<<<(M * D_ / 8 + 255) / 256, 256>>>(x, xh, M * D_ / 8);
    zero_rs_kernel<<<(B_ * T_ + 255) / 256, 256>>>(rs, B_ * T_);
    transpose_f2h3<<<dim3(D_ / 32, D_ / 32, 3), dim3(32, 8)>>>(Wq, Wk, Wv, wt, D_, D_, DD);

    // 1) fused QKV projections (one launch, z selects q/k/v), fp16 out
    dim3 gProj(D_ / BN, M / BM, 3);
    gemm_h<true, true, false, false, false, false, true><<<gProj, 256, SMEM_BYTES>>>(
        xh, wt, bq, bk, bv, qkv, nullptr, M, D_, D_, 1.f, 0, DD, (size_t)M * D_);

    // 2) v^T (per batch), fp16
    transpose_h2h<<<dim3(D_ / 32, T_ / 32, B_), dim3(32, 8)>>>(v, vt, T_, D_, TD, TD);

    // 3) E = exp(Q K^T / 32) fp16 (lower-triangle tiles only, diagonal masked),
    //    row sums accumulated into rs via atomics. Softmax kernel eliminated.
    dim3 gS(T_ / BN, T_ / BM, B_);
    gemm_h<false, false, true, false, true, false, true><<<gS, 256, SMEM_BYTES>>>(
        q, k, nullptr, nullptr, nullptr, p, rs, T_, T_, D_, 1.0f / 32.0f, TD, TD, TT);

    // 4) out = (E @ V) / rs with causal K-limit, heavy-first m order, fp32 out
    dim3 gPV(D_ / BN, T_ / BM, B_);
    gemm_h<false, false, false, true, false, true, false><<<gPV, 256, SMEM_BYTES>>>(
        p, vt, nullptr, nullptr, nullptr, out, rs, T_, D_, T_, 1.f, TT, TD, TD);
}